// round 11
// baseline (speedup 1.0000x reference)
#include <cuda_runtime.h>
#include <math.h>
#include <stdint.h>

#define BB 4
#define SS 1024
#define DD 1024
#define HH 16
#define HDIM 64
#define MROWS (BB*SS)   /* 4096 */
#define FFD (4*DD)      /* 4096 */
#define LN_EPS 1e-5f

/* ---------------- scratch pool ---------------- */
#define OFF_Q   (0ul)
#define OFF_K   (4ul<<20)
#define OFF_V   (8ul<<20)
#define OFF_CTX (12ul<<20)
#define OFF_X1  (16ul<<20)
#define OFF_TMP (20ul<<20)
#define OFF_H   (24ul<<20)
#define OFF_MW  (40ul<<20)          /* packed mask words, 2M uint32 */
#define POOL_FLOATS (44ul<<20)
__device__ __align__(256) float g_pool[POOL_FLOATS];

/* ---------------- helpers ---------------- */
__device__ __forceinline__ float to_tf32(float x) {
    uint32_t r;
    asm("cvt.rna.tf32.f32 %0, %1;" : "=r"(r) : "f"(x));
    return __uint_as_float(r);
}
__device__ __forceinline__ void mma_tf32(float c[4],
                                         uint32_t a0, uint32_t a1, uint32_t a2, uint32_t a3,
                                         uint32_t b0, uint32_t b1) {
    asm volatile(
        "mma.sync.aligned.m16n8k8.row.col.f32.tf32.tf32.f32 "
        "{%0,%1,%2,%3}, {%4,%5,%6,%7}, {%8,%9}, {%0,%1,%2,%3};"
        : "+f"(c[0]), "+f"(c[1]), "+f"(c[2]), "+f"(c[3])
        : "r"(a0), "r"(a1), "r"(a2), "r"(a3), "r"(b0), "r"(b1));
}
__device__ __forceinline__ uint32_t fu(float x) { return __float_as_uint(x); }

__device__ __forceinline__ void cp_async16(void* dst, const void* src) {
    uint32_t s = (uint32_t)__cvta_generic_to_shared(dst);
    asm volatile("cp.async.cg.shared.global [%0], [%1], 16;\n" :: "r"(s), "l"(src));
}
#define CP_COMMIT() asm volatile("cp.async.commit_group;\n" ::: "memory")
#define CP_WAIT0()  asm volatile("cp.async.wait_group 0;\n" ::: "memory")

__device__ __forceinline__ float warpSum(float v) {
    #pragma unroll
    for (int o = 16; o; o >>= 1) v += __shfl_xor_sync(0xffffffffu, v, o);
    return v;
}
__device__ __forceinline__ float blockSum(float v, float* red) {
    int lane = threadIdx.x & 31, w = threadIdx.x >> 5;
    v = warpSum(v);
    __syncthreads();
    if (lane == 0) red[w] = v;
    __syncthreads();
    float r = (lane < 8) ? red[lane] : 0.f;
    return warpSum(r);
}

/* =====================================================================
   mask_pack: int32 mask -> 1 bit per element.
   ===================================================================== */
__global__ void __launch_bounds__(256)
mask_pack(const int* __restrict__ mask, uint32_t* __restrict__ mw)
{
    const int warp = (blockIdx.x * blockDim.x + threadIdx.x) >> 5;
    const int lane = threadIdx.x & 31;
    const size_t base = (size_t)warp * 256;
    uint32_t w[8];
    #pragma unroll
    for (int i = 0; i < 8; i++) {
        int v = mask[base + i * 32 + lane];
        w[i] = __ballot_sync(0xffffffffu, v != 0);
    }
    if (lane == 0) {
        uint4 lo; lo.x = w[0]; lo.y = w[1]; lo.z = w[2]; lo.w = w[3];
        uint4 hi; hi.x = w[4]; hi.y = w[5]; hi.z = w[6]; hi.w = w[7];
        *(uint4*)&mw[(size_t)warp * 8]     = lo;
        *(uint4*)&mw[(size_t)warp * 8 + 4] = hi;
    }
}

/* =====================================================================
   Dense GEMM, 2-stage cp.async pipeline + register-double-buffered
   fragments, tf32 mma. CTA 128x128, 256 thr, warp 64x32, K step 32.
   ===================================================================== */
#define LDA 36
#define LDB 136
#define AS_TILE (128*LDA)
#define BS_TILE (32*LDB)
#define GEMM_SMEM ((2*AS_TILE + 2*BS_TILE)*4)

__device__ __forceinline__ void load_af(uint32_t af[4][4], const float* Ab,
                                        int kk, int wm, int g, int t)
{
    #pragma unroll
    for (int mt = 0; mt < 4; mt++) {
        int mb = wm * 64 + mt * 16 + g;
        af[mt][0] = fu(Ab[mb * LDA + kk + t]);
        af[mt][1] = fu(Ab[(mb + 8) * LDA + kk + t]);
        af[mt][2] = fu(Ab[mb * LDA + kk + t + 4]);
        af[mt][3] = fu(Ab[(mb + 8) * LDA + kk + t + 4]);
    }
}
__device__ __forceinline__ void load_bf(uint32_t bf[4][2], const float* Bb,
                                        int kk, int wn, int g, int t)
{
    #pragma unroll
    for (int nt = 0; nt < 4; nt++) {
        int nb = wn * 32 + nt * 8 + g;
        bf[nt][0] = fu(Bb[(kk + t) * LDB + nb]);
        bf[nt][1] = fu(Bb[(kk + t + 4) * LDB + nb]);
    }
}
__device__ __forceinline__ void mma_set(float acc[4][4][4],
                                        uint32_t af[4][4], uint32_t bf[4][2])
{
    #pragma unroll
    for (int mt = 0; mt < 4; mt++)
        #pragma unroll
        for (int nt = 0; nt < 4; nt++)
            mma_tf32(acc[mt][nt], af[mt][0], af[mt][1], af[mt][2], af[mt][3],
                     bf[nt][0], bf[nt][1]);
}

template<int EPI>
__device__ __forceinline__ void
gemm_body(const float* __restrict__ A, const float* __restrict__ W,
          const float* __restrict__ bias, const float* __restrict__ res,
          float* __restrict__ C, int M, int N, int K)
{
    extern __shared__ float sm[];
    float* As = sm;
    float* Bs = sm + 2*AS_TILE;

    const int tid = threadIdx.x;
    const int wid = tid >> 5, lane = tid & 31;
    const int g = lane >> 2, t = lane & 3;
    const int wm = wid >> 2, wn = wid & 3;
    const int row0 = blockIdx.y * 128;
    const int col0 = blockIdx.x * 128;

    float acc[4][4][4];
    #pragma unroll
    for (int mt = 0; mt < 4; mt++)
        #pragma unroll
        for (int nt = 0; nt < 4; nt++)
            #pragma unroll
            for (int i = 0; i < 4; i++) acc[mt][nt][i] = 0.f;

    #pragma unroll
    for (int i = 0; i < 4; i++) {
        int idx = tid + i * 256;
        int m = idx >> 3, kc = (idx & 7) * 4;
        cp_async16(&As[m * LDA + kc], &A[(size_t)(row0 + m) * K + kc]);
    }
    #pragma unroll
    for (int i = 0; i < 4; i++) {
        int idx = tid + i * 256;
        int kr = idx >> 5, nc = (idx & 31) * 4;
        cp_async16(&Bs[kr * LDB + nc], &W[(size_t)kr * N + col0 + nc]);
    }
    CP_COMMIT();

    const int nit = K >> 5;
    for (int it = 0; it < nit; it++) {
        const int buf = it & 1;
        const float* Ab = As + buf * AS_TILE;
        const float* Bb = Bs + buf * BS_TILE;
        CP_WAIT0();
        __syncthreads();

        if (it + 1 < nit) {
            const int k0 = (it + 1) << 5;
            float* An = As + (buf ^ 1) * AS_TILE;
            float* Bn = Bs + (buf ^ 1) * BS_TILE;
            #pragma unroll
            for (int i = 0; i < 4; i++) {
                int idx = tid + i * 256;
                int m = idx >> 3, kc = (idx & 7) * 4;
                cp_async16(&An[m * LDA + kc], &A[(size_t)(row0 + m) * K + k0 + kc]);
            }
            #pragma unroll
            for (int i = 0; i < 4; i++) {
                int idx = tid + i * 256;
                int kr = idx >> 5, nc = (idx & 31) * 4;
                cp_async16(&Bn[kr * LDB + nc], &W[(size_t)(k0 + kr) * N + col0 + nc]);
            }
            CP_COMMIT();
        }

        /* register-double-buffered fragment pipeline over kk = 0,8,16,24 */
        {
            uint32_t af0[4][4], bf0[4][2], af1[4][4], bf1[4][2];
            load_af(af0, Ab, 0, wm, g, t);  load_bf(bf0, Bb, 0, wn, g, t);
            load_af(af1, Ab, 8, wm, g, t);  load_bf(bf1, Bb, 8, wn, g, t);
            mma_set(acc, af0, bf0);
            load_af(af0, Ab, 16, wm, g, t); load_bf(bf0, Bb, 16, wn, g, t);
            mma_set(acc, af1, bf1);
            load_af(af1, Ab, 24, wm, g, t); load_bf(bf1, Bb, 24, wn, g, t);
            mma_set(acc, af0, bf0);
            mma_set(acc, af1, bf1);
        }
        __syncthreads();
    }

    #pragma unroll
    for (int mt = 0; mt < 4; mt++) {
        #pragma unroll
        for (int half = 0; half < 2; half++) {
            const int r = row0 + wm * 64 + mt * 16 + g + half * 8;
            #pragma unroll
            for (int nt = 0; nt < 4; nt++) {
                const int c = col0 + wn * 32 + nt * 8 + 2 * t;
                float v0 = acc[mt][nt][half * 2 + 0];
                float v1 = acc[mt][nt][half * 2 + 1];
                float2 bv = *(const float2*)&bias[c];
                v0 += bv.x; v1 += bv.y;
                if (EPI == 1) { v0 = fmaxf(v0, 0.f); v1 = fmaxf(v1, 0.f); }
                if (EPI == 2) {
                    float2 rv = *(const float2*)&res[(size_t)r * N + c];
                    v0 += rv.x; v1 += rv.y;
                }
                float2 o; o.x = v0; o.y = v1;
                *(float2*)&C[(size_t)r * N + c] = o;
            }
        }
    }
}

template<int EPI>
__global__ void __launch_bounds__(256, 2)
mma_gemm(const float* __restrict__ A, const float* __restrict__ W,
         const float* __restrict__ bias, const float* __restrict__ res,
         float* __restrict__ C, int M, int N, int K)
{
    gemm_body<EPI>(A, W, bias, res, C, M, N, K);
}

/* Q, K, V projections in one launch: grid.z picks the set */
__global__ void __launch_bounds__(256, 2)
mma_gemm_qkv(const float* __restrict__ x, const float* __restrict__ y,
             const float* __restrict__ Wq, const float* __restrict__ bq, float* __restrict__ qo,
             const float* __restrict__ Wk, const float* __restrict__ bk, float* __restrict__ ko,
             const float* __restrict__ Wv, const float* __restrict__ bv, float* __restrict__ vo,
             int M, int N, int K)
{
    if (blockIdx.z == 0)      gemm_body<0>(x, Wq, bq, nullptr, qo, M, N, K);
    else if (blockIdx.z == 1) gemm_body<0>(y, Wk, bk, nullptr, ko, M, N, K);
    else                      gemm_body<0>(y, Wv, bv, nullptr, vo, M, N, K);
}

/* =====================================================================
   Fused attention, no-max softmax, bitmask in smem (unchanged from R9).
   ===================================================================== */
#define LDQ 68
#define LDV 72
#define LDP 36
#define LDM 36
#define KTR 32
#define KS_T (KTR*LDQ)
#define VS_T (KTR*LDV)
#define FL_SMEM ((128*LDQ + 2*KS_T + 2*VS_T + 128*LDP + 128*LDM + 128)*4)

__global__ void __launch_bounds__(256, 2)
flash_attn(const float* __restrict__ Q, const float* __restrict__ Kg,
           const float* __restrict__ Vg, const uint32_t* __restrict__ mw,
           float* __restrict__ ctx)
{
    extern __shared__ float sm[];
    float* Qs = sm;
    float* Ks = Qs + 128 * LDQ;
    float* Vs = Ks + 2 * KS_T;
    float* Ps = Vs + 2 * VS_T;
    uint32_t* Mw = (uint32_t*)(Ps + 128 * LDP);
    float* rsum = (float*)(Mw + 128 * LDM);

    const int tid = threadIdx.x;
    const int wid = tid >> 5, lane = tid & 31;
    const int g = lane >> 2, t = lane & 3;
    const int wm = wid >> 2, wn = wid & 3;
    const int q0 = blockIdx.x * 128;
    const int bh = blockIdx.y;
    const int b = bh >> 4, h = bh & 15;

    if (tid < 128) rsum[tid] = 0.f;

    const float* Qbase = Q + ((size_t)(b * SS + q0)) * DD + h * HDIM;
    const float* Kb0 = Kg + ((size_t)b * SS) * DD + h * HDIM;
    const float* Vb0 = Vg + ((size_t)b * SS) * DD + h * HDIM;
    const uint32_t* Mbase = mw + ((size_t)(bh * SS + q0)) * 32;

    #pragma unroll
    for (int i = 0; i < 8; i++) {
        int idx = tid + i * 256;
        int m = idx >> 4, c = (idx & 15) * 4;
        cp_async16(&Qs[m * LDQ + c], Qbase + (size_t)m * DD + c);
    }
    #pragma unroll
    for (int i = 0; i < 4; i++) {
        int idx = tid + i * 256;
        int m = idx >> 3, c = (idx & 7) * 4;
        cp_async16(&Mw[m * LDM + c], Mbase + (size_t)m * 32 + c);
    }
    #pragma unroll
    for (int i = 0; i < 2; i++) {
        int idx = tid + i * 256;
        int r = idx >> 4, c = (idx & 15) * 4;
        cp_async16(&Ks[r * LDQ + c], Kb0 + (size_t)r * DD + c);
        cp_async16(&Vs[r * LDV + c], Vb0 + (size_t)r * DD + c);
    }
    CP_COMMIT();

    float acc_o[4][2][4];
    #pragma unroll
    for (int mt = 0; mt < 4; mt++)
        #pragma unroll
        for (int nt = 0; nt < 2; nt++)
            #pragma unroll
            for (int i = 0; i < 4; i++) acc_o[mt][nt][i] = 0.f;
    float rs[8];
    #pragma unroll
    for (int i = 0; i < 8; i++) rs[i] = 0.f;

    const int nkt = SS / KTR;
    for (int kt = 0; kt < nkt; kt++) {
        const int buf = kt & 1;
        const float* Kb = Ks + buf * KS_T;
        const float* Vb = Vs + buf * VS_T;

        CP_WAIT0();
        __syncthreads();

        if (kt + 1 < nkt) {
            float* Kn = Ks + (buf ^ 1) * KS_T;
            float* Vn = Vs + (buf ^ 1) * VS_T;
            const float* Kt = Kb0 + (size_t)((kt + 1) * KTR) * DD;
            const float* Vt = Vb0 + (size_t)((kt + 1) * KTR) * DD;
            #pragma unroll
            for (int i = 0; i < 2; i++) {
                int idx = tid + i * 256;
                int r = idx >> 4, c = (idx & 15) * 4;
                cp_async16(&Kn[r * LDQ + c], Kt + (size_t)r * DD + c);
                cp_async16(&Vn[r * LDV + c], Vt + (size_t)r * DD + c);
            }
            CP_COMMIT();
        }

        float acc_s[4][4];
        #pragma unroll
        for (int mt = 0; mt < 4; mt++)
            #pragma unroll
            for (int i = 0; i < 4; i++) acc_s[mt][i] = 0.f;

        #pragma unroll
        for (int kk = 0; kk < 64; kk += 8) {
            uint32_t af[4][4], bf[2];
            #pragma unroll
            for (int mt = 0; mt < 4; mt++) {
                int mb = wm * 64 + mt * 16 + g;
                af[mt][0] = fu(Qs[mb * LDQ + kk + t]);
                af[mt][1] = fu(Qs[(mb + 8) * LDQ + kk + t]);
                af[mt][2] = fu(Qs[mb * LDQ + kk + t + 4]);
                af[mt][3] = fu(Qs[(mb + 8) * LDQ + kk + t + 4]);
            }
            {
                int nb = wn * 8 + g;
                bf[0] = fu(Kb[nb * LDQ + kk + t]);
                bf[1] = fu(Kb[nb * LDQ + kk + t + 4]);
            }
            #pragma unroll
            for (int mt = 0; mt < 4; mt++)
                mma_tf32(acc_s[mt], af[mt][0], af[mt][1], af[mt][2], af[mt][3],
                         bf[0], bf[1]);
        }

        const int col = wn * 8 + 2 * t;
        #pragma unroll
        for (int mt = 0; mt < 4; mt++) {
            #pragma unroll
            for (int half = 0; half < 2; half++) {
                const int row = wm * 64 + mt * 16 + g + half * 8;
                const uint32_t word = Mw[row * LDM + kt];
                float s0 = acc_s[mt][half * 2 + 0] * 0.125f;
                float s1 = acc_s[mt][half * 2 + 1] * 0.125f;
                float p0 = ((word >> col) & 1u) ? 0.f : __expf(s0);
                float p1 = ((word >> (col + 1)) & 1u) ? 0.f : __expf(s1);
                rs[mt * 2 + half] += p0 + p1;
                float2 pv; pv.x = to_tf32(p0); pv.y = to_tf32(p1);
                *(float2*)&Ps[row * LDP + col] = pv;
            }
        }
        __syncthreads();

        #pragma unroll
        for (int kk = 0; kk < 32; kk += 8) {
            uint32_t af[4][4], bf[2][2];
            #pragma unroll
            for (int mt = 0; mt < 4; mt++) {
                int mb = wm * 64 + mt * 16 + g;
                af[mt][0] = fu(Ps[mb * LDP + kk + t]);
                af[mt][1] = fu(Ps[(mb + 8) * LDP + kk + t]);
                af[mt][2] = fu(Ps[mb * LDP + kk + t + 4]);
                af[mt][3] = fu(Ps[(mb + 8) * LDP + kk + t + 4]);
            }
            #pragma unroll
            for (int nt = 0; nt < 2; nt++) {
                int nb = wn * 16 + nt * 8 + g;
                bf[nt][0] = fu(Vb[(kk + t) * LDV + nb]);
                bf[nt][1] = fu(Vb[(kk + t + 4) * LDV + nb]);
            }
            #pragma unroll
            for (int mt = 0; mt < 4; mt++)
                #pragma unroll
                for (int nt = 0; nt < 2; nt++)
                    mma_tf32(acc_o[mt][nt], af[mt][0], af[mt][1], af[mt][2], af[mt][3],
                             bf[nt][0], bf[nt][1]);
        }
    }

    #pragma unroll
    for (int mt = 0; mt < 4; mt++)
        #pragma unroll
        for (int half = 0; half < 2; half++) {
            const int row = wm * 64 + mt * 16 + g + half * 8;
            atomicAdd(&rsum[row], rs[mt * 2 + half]);
        }
    __syncthreads();

    #pragma unroll
    for (int mt = 0; mt < 4; mt++) {
        #pragma unroll
        for (int half = 0; half < 2; half++) {
            const int row = wm * 64 + mt * 16 + g + half * 8;
            const float inv = 1.f / rsum[row];
            #pragma unroll
            for (int nt = 0; nt < 2; nt++) {
                const int c = wn * 16 + nt * 8 + 2 * t;
                float2 o;
                o.x = acc_o[mt][nt][half * 2 + 0] * inv;
                o.y = acc_o[mt][nt][half * 2 + 1] * inv;
                *(float2*)&ctx[((size_t)(b * SS + q0 + row)) * DD + h * HDIM + c] = o;
            }
        }
    }
}

/* ---------------- LayerNorm over D ---------------- */
__global__ void __launch_bounds__(256)
ln_kernel(const float* __restrict__ in, const float* __restrict__ g,
          const float* __restrict__ beta, float* __restrict__ out)
{
    __shared__ float red[8];
    const size_t base = (size_t)blockIdx.x * DD;
    const int tid = threadIdx.x;
    float v[4];
    #pragma unroll
    for (int i = 0; i < 4; i++) v[i] = in[base + tid + i * 256];

    float s = v[0] + v[1] + v[2] + v[3];
    const float mu = blockSum(s, red) * (1.f / DD);

    float sq = 0.f;
    #pragma unroll
    for (int i = 0; i < 4; i++) { v[i] -= mu; sq += v[i] * v[i]; }
    const float var = blockSum(sq, red) * (1.f / DD);
    const float r = rsqrtf(var + LN_EPS);

    #pragma unroll
    for (int i = 0; i < 4; i++) {
        int c = tid + i * 256;
        out[base + c] = v[i] * r * g[c] + beta[c];
    }
}

/* ---------------- launch ---------------- */
extern "C" void kernel_launch(void* const* d_in, const int* in_sizes, int n_in,
                              void* d_out, int out_size)
{
    const float* x    = (const float*)d_in[0];
    const float* y    = (const float*)d_in[1];
    const int* mask   = (const int*)d_in[2];
    const float* Wq = (const float*)d_in[3];
    const float* bq = (const float*)d_in[4];
    const float* Wk = (const float*)d_in[5];
    const float* bk = (const float*)d_in[6];
    const float* Wv = (const float*)d_in[7];
    const float* bv = (const float*)d_in[8];
    const float* Wo = (const float*)d_in[9];
    const float* bo = (const float*)d_in[10];
    const float* W1 = (const float*)d_in[11];
    const float* b1 = (const float*)d_in[12];
    const float* W2 = (const float*)d_in[13];
    const float* b2 = (const float*)d_in[14];
    const float* g1 = (const float*)d_in[15];
    const float* be1 = (const float*)d_in[16];
    const float* g2 = (const float*)d_in[17];
    const float* be2 = (const float*)d_in[18];
    float* out = (float*)d_out;

    cudaFuncSetAttribute(mma_gemm<0>, cudaFuncAttributeMaxDynamicSharedMemorySize, GEMM_SMEM);
    cudaFuncSetAttribute(mma_gemm<1>, cudaFuncAttributeMaxDynamicSharedMemorySize, GEMM_SMEM);
    cudaFuncSetAttribute(mma_gemm<2>, cudaFuncAttributeMaxDynamicSharedMemorySize, GEMM_SMEM);
    cudaFuncSetAttribute(mma_gemm_qkv, cudaFuncAttributeMaxDynamicSharedMemorySize, GEMM_SMEM);
    cudaFuncSetAttribute(flash_attn, cudaFuncAttributeMaxDynamicSharedMemorySize, FL_SMEM);

    float* pool = nullptr;
    cudaGetSymbolAddress((void**)&pool, g_pool);
    float* q   = pool + OFF_Q;
    float* k   = pool + OFF_K;
    float* v   = pool + OFF_V;
    float* ctx = pool + OFF_CTX;
    float* x1  = pool + OFF_X1;
    float* tmp = pool + OFF_TMP;
    float* h   = pool + OFF_H;
    uint32_t* mw = (uint32_t*)(pool + OFF_MW);

    dim3 gProj(DD / 128, MROWS / 128);      /* 8 x 32 */
    dim3 gQKV(DD / 128, MROWS / 128, 3);    /* 8 x 32 x 3 */
    dim3 gFF1(FFD / 128, MROWS / 128);      /* 32 x 32 */

    /* mask packing */
    mask_pack<<<32768, 256>>>(mask, mw);

    /* QKV projections, one launch */
    mma_gemm_qkv<<<gQKV, 256, GEMM_SMEM>>>(x, y, Wq, bq, q, Wk, bk, k,
                                           Wv, bv, v, MROWS, DD, DD);

    /* fused attention */
    flash_attn<<<dim3(SS / 128, BB * HH), 256, FL_SMEM>>>(q, k, v, mw, ctx);

    /* output proj + residual, LN1 */
    mma_gemm<2><<<gProj, 256, GEMM_SMEM>>>(ctx, Wo, bo, x, tmp, MROWS, DD, DD);
    ln_kernel<<<MROWS, 256>>>(tmp, g1, be1, x1);

    /* FFN */
    mma_gemm<1><<<gFF1, 256, GEMM_SMEM>>>(x1, W1, b1, nullptr, h, MROWS, FFD, DD);
    mma_gemm<2><<<gProj, 256, GEMM_SMEM>>>(h, W2, b2, x1, tmp, MROWS, DD, FFD);
    ln_kernel<<<MROWS, 256>>>(tmp, g2, be2, out);
}

// round 12
// speedup vs baseline: 1.0504x; 1.0504x over previous
#include <cuda_runtime.h>
#include <math.h>
#include <stdint.h>

#define BB 4
#define SS 1024
#define DD 1024
#define HH 16
#define HDIM 64
#define MROWS (BB*SS)   /* 4096 */
#define FFD (4*DD)      /* 4096 */
#define LN_EPS 1e-5f

/* ---------------- scratch pool ---------------- */
#define OFF_Q   (0ul)
#define OFF_K   (4ul<<20)
#define OFF_V   (8ul<<20)
#define OFF_CTX (12ul<<20)
#define OFF_X1  (16ul<<20)
#define OFF_TMP (20ul<<20)
#define OFF_H   (24ul<<20)
#define OFF_MW  (40ul<<20)          /* packed mask words, 2M uint32 */
#define POOL_FLOATS (44ul<<20)
__device__ __align__(256) float g_pool[POOL_FLOATS];

/* ---------------- helpers ---------------- */
__device__ __forceinline__ float to_tf32(float x) {
    uint32_t r;
    asm("cvt.rna.tf32.f32 %0, %1;" : "=r"(r) : "f"(x));
    return __uint_as_float(r);
}
__device__ __forceinline__ void mma_tf32(float c[4],
                                         uint32_t a0, uint32_t a1, uint32_t a2, uint32_t a3,
                                         uint32_t b0, uint32_t b1) {
    asm volatile(
        "mma.sync.aligned.m16n8k8.row.col.f32.tf32.tf32.f32 "
        "{%0,%1,%2,%3}, {%4,%5,%6,%7}, {%8,%9}, {%0,%1,%2,%3};"
        : "+f"(c[0]), "+f"(c[1]), "+f"(c[2]), "+f"(c[3])
        : "r"(a0), "r"(a1), "r"(a2), "r"(a3), "r"(b0), "r"(b1));
}
__device__ __forceinline__ uint32_t fu(float x) { return __float_as_uint(x); }

__device__ __forceinline__ void cp_async16(void* dst, const void* src) {
    uint32_t s = (uint32_t)__cvta_generic_to_shared(dst);
    asm volatile("cp.async.cg.shared.global [%0], [%1], 16;\n" :: "r"(s), "l"(src));
}
#define CP_COMMIT() asm volatile("cp.async.commit_group;\n" ::: "memory")
#define CP_WAIT0()  asm volatile("cp.async.wait_group 0;\n" ::: "memory")

__device__ __forceinline__ float warpSum(float v) {
    #pragma unroll
    for (int o = 16; o; o >>= 1) v += __shfl_xor_sync(0xffffffffu, v, o);
    return v;
}
__device__ __forceinline__ float blockSum(float v, float* red) {
    int lane = threadIdx.x & 31, w = threadIdx.x >> 5;
    v = warpSum(v);
    __syncthreads();
    if (lane == 0) red[w] = v;
    __syncthreads();
    float r = (lane < 8) ? red[lane] : 0.f;
    return warpSum(r);
}

/* =====================================================================
   mask_pack: int32 mask -> 1 bit per element.
   ===================================================================== */
__global__ void __launch_bounds__(256)
mask_pack(const int* __restrict__ mask, uint32_t* __restrict__ mw)
{
    const int warp = (blockIdx.x * blockDim.x + threadIdx.x) >> 5;
    const int lane = threadIdx.x & 31;
    const size_t base = (size_t)warp * 256;
    uint32_t w[8];
    #pragma unroll
    for (int i = 0; i < 8; i++) {
        int v = mask[base + i * 32 + lane];
        w[i] = __ballot_sync(0xffffffffu, v != 0);
    }
    if (lane == 0) {
        uint4 lo; lo.x = w[0]; lo.y = w[1]; lo.z = w[2]; lo.w = w[3];
        uint4 hi; hi.x = w[4]; hi.y = w[5]; hi.z = w[6]; hi.w = w[7];
        *(uint4*)&mw[(size_t)warp * 8]     = lo;
        *(uint4*)&mw[(size_t)warp * 8 + 4] = hi;
    }
}

/* =====================================================================
   Dense GEMM, 2-stage cp.async + reg-double-buffered frags, tf32 mma.
   CTA 128x128, 256 thr, warp 64x32, K step 32.
   k-lane remap: lanes (t, t+4) hold global k (2t, 2t+1) -> A frag = LDS.64.
   LDA=40 (A rows 32+8 pad, 8g+2t bank bijection), LDB=132 (8t+g bijection).
   ===================================================================== */
#define LDA 40
#define LDB 132
#define AS_TILE (128*LDA)
#define BS_TILE (32*LDB)
#define GEMM_SMEM ((2*AS_TILE + 2*BS_TILE)*4)

__device__ __forceinline__ void load_af(uint32_t af[4][4], const float* Ab,
                                        int kk, int wm, int g, int t)
{
    #pragma unroll
    for (int mt = 0; mt < 4; mt++) {
        int mb = wm * 64 + mt * 16 + g;
        float2 p0 = *(const float2*)&Ab[mb * LDA + kk + 2 * t];
        float2 p1 = *(const float2*)&Ab[(mb + 8) * LDA + kk + 2 * t];
        af[mt][0] = fu(p0.x); af[mt][2] = fu(p0.y);
        af[mt][1] = fu(p1.x); af[mt][3] = fu(p1.y);
    }
}
__device__ __forceinline__ void load_bf(uint32_t bf[4][2], const float* Bb,
                                        int kk, int wn, int g, int t)
{
    #pragma unroll
    for (int nt = 0; nt < 4; nt++) {
        int nb = wn * 32 + nt * 8 + g;
        bf[nt][0] = fu(Bb[(kk + 2 * t) * LDB + nb]);
        bf[nt][1] = fu(Bb[(kk + 2 * t + 1) * LDB + nb]);
    }
}
__device__ __forceinline__ void mma_set(float acc[4][4][4],
                                        uint32_t af[4][4], uint32_t bf[4][2])
{
    #pragma unroll
    for (int mt = 0; mt < 4; mt++)
        #pragma unroll
        for (int nt = 0; nt < 4; nt++)
            mma_tf32(acc[mt][nt], af[mt][0], af[mt][1], af[mt][2], af[mt][3],
                     bf[nt][0], bf[nt][1]);
}

template<int EPI>
__device__ __forceinline__ void
gemm_body(const float* __restrict__ A, const float* __restrict__ W,
          const float* __restrict__ bias, const float* __restrict__ res,
          float* __restrict__ C, int M, int N, int K)
{
    extern __shared__ float sm[];
    float* As = sm;
    float* Bs = sm + 2*AS_TILE;

    const int tid = threadIdx.x;
    const int wid = tid >> 5, lane = tid & 31;
    const int g = lane >> 2, t = lane & 3;
    const int wm = wid >> 2, wn = wid & 3;
    const int row0 = blockIdx.y * 128;
    const int col0 = blockIdx.x * 128;

    float acc[4][4][4];
    #pragma unroll
    for (int mt = 0; mt < 4; mt++)
        #pragma unroll
        for (int nt = 0; nt < 4; nt++)
            #pragma unroll
            for (int i = 0; i < 4; i++) acc[mt][nt][i] = 0.f;

    #pragma unroll
    for (int i = 0; i < 4; i++) {
        int idx = tid + i * 256;
        int m = idx >> 3, kc = (idx & 7) * 4;
        cp_async16(&As[m * LDA + kc], &A[(size_t)(row0 + m) * K + kc]);
    }
    #pragma unroll
    for (int i = 0; i < 4; i++) {
        int idx = tid + i * 256;
        int kr = idx >> 5, nc = (idx & 31) * 4;
        cp_async16(&Bs[kr * LDB + nc], &W[(size_t)kr * N + col0 + nc]);
    }
    CP_COMMIT();

    const int nit = K >> 5;
    for (int it = 0; it < nit; it++) {
        const int buf = it & 1;
        const float* Ab = As + buf * AS_TILE;
        const float* Bb = Bs + buf * BS_TILE;
        CP_WAIT0();
        __syncthreads();

        if (it + 1 < nit) {
            const int k0 = (it + 1) << 5;
            float* An = As + (buf ^ 1) * AS_TILE;
            float* Bn = Bs + (buf ^ 1) * BS_TILE;
            #pragma unroll
            for (int i = 0; i < 4; i++) {
                int idx = tid + i * 256;
                int m = idx >> 3, kc = (idx & 7) * 4;
                cp_async16(&An[m * LDA + kc], &A[(size_t)(row0 + m) * K + k0 + kc]);
            }
            #pragma unroll
            for (int i = 0; i < 4; i++) {
                int idx = tid + i * 256;
                int kr = idx >> 5, nc = (idx & 31) * 4;
                cp_async16(&Bn[kr * LDB + nc], &W[(size_t)(k0 + kr) * N + col0 + nc]);
            }
            CP_COMMIT();
        }

        /* register-double-buffered fragment pipeline over kk = 0,8,16,24 */
        {
            uint32_t af0[4][4], bf0[4][2], af1[4][4], bf1[4][2];
            load_af(af0, Ab, 0, wm, g, t);  load_bf(bf0, Bb, 0, wn, g, t);
            load_af(af1, Ab, 8, wm, g, t);  load_bf(bf1, Bb, 8, wn, g, t);
            mma_set(acc, af0, bf0);
            load_af(af0, Ab, 16, wm, g, t); load_bf(bf0, Bb, 16, wn, g, t);
            mma_set(acc, af1, bf1);
            load_af(af1, Ab, 24, wm, g, t); load_bf(bf1, Bb, 24, wn, g, t);
            mma_set(acc, af0, bf0);
            mma_set(acc, af1, bf1);
        }
        __syncthreads();
    }

    #pragma unroll
    for (int mt = 0; mt < 4; mt++) {
        #pragma unroll
        for (int half = 0; half < 2; half++) {
            const int r = row0 + wm * 64 + mt * 16 + g + half * 8;
            #pragma unroll
            for (int nt = 0; nt < 4; nt++) {
                const int c = col0 + wn * 32 + nt * 8 + 2 * t;
                float v0 = acc[mt][nt][half * 2 + 0];
                float v1 = acc[mt][nt][half * 2 + 1];
                float2 bv = *(const float2*)&bias[c];
                v0 += bv.x; v1 += bv.y;
                if (EPI == 1) { v0 = fmaxf(v0, 0.f); v1 = fmaxf(v1, 0.f); }
                if (EPI == 2) {
                    float2 rv = *(const float2*)&res[(size_t)r * N + c];
                    v0 += rv.x; v1 += rv.y;
                }
                float2 o; o.x = v0; o.y = v1;
                *(float2*)&C[(size_t)r * N + c] = o;
            }
        }
    }
}

template<int EPI>
__global__ void __launch_bounds__(256, 2)
mma_gemm(const float* __restrict__ A, const float* __restrict__ W,
         const float* __restrict__ bias, const float* __restrict__ res,
         float* __restrict__ C, int M, int N, int K)
{
    gemm_body<EPI>(A, W, bias, res, C, M, N, K);
}

/* K and V projections share A=y; grid.z picks the weight/output set */
__global__ void __launch_bounds__(256, 2)
mma_gemm_kv(const float* __restrict__ y,
            const float* __restrict__ Wk, const float* __restrict__ bk, float* __restrict__ ko,
            const float* __restrict__ Wv, const float* __restrict__ bv, float* __restrict__ vo,
            int M, int N, int K)
{
    if (blockIdx.z == 0) gemm_body<0>(y, Wk, bk, nullptr, ko, M, N, K);
    else                 gemm_body<0>(y, Wv, bv, nullptr, vo, M, N, K);
}

/* =====================================================================
   Fused attention, no-max softmax, bitmask in smem, k-pair LDS.64 frags.
   LDQ=72 (Q/K rows, 8g+2t bijection), LDV=68 (8t+g), LDP=40 (8g+2t).
   ===================================================================== */
#define LDQ 72
#define LDV 68
#define LDP 40
#define LDM 36
#define KTR 32
#define KS_T (KTR*LDQ)
#define VS_T (KTR*LDV)
#define FL_SMEM ((128*LDQ + 2*KS_T + 2*VS_T + 128*LDP + 128*LDM + 128)*4)

__global__ void __launch_bounds__(256, 2)
flash_attn(const float* __restrict__ Q, const float* __restrict__ Kg,
           const float* __restrict__ Vg, const uint32_t* __restrict__ mw,
           float* __restrict__ ctx)
{
    extern __shared__ float sm[];
    float* Qs = sm;                         /* [128][72] */
    float* Ks = Qs + 128 * LDQ;             /* [2][32][72] */
    float* Vs = Ks + 2 * KS_T;              /* [2][32][68] */
    float* Ps = Vs + 2 * VS_T;              /* [128][40] */
    uint32_t* Mw = (uint32_t*)(Ps + 128 * LDP);  /* [128][36] */
    float* rsum = (float*)(Mw + 128 * LDM);      /* [128] */

    const int tid = threadIdx.x;
    const int wid = tid >> 5, lane = tid & 31;
    const int g = lane >> 2, t = lane & 3;
    const int wm = wid >> 2, wn = wid & 3;
    const int q0 = blockIdx.x * 128;
    const int bh = blockIdx.y;
    const int b = bh >> 4, h = bh & 15;

    if (tid < 128) rsum[tid] = 0.f;

    const float* Qbase = Q + ((size_t)(b * SS + q0)) * DD + h * HDIM;
    const float* Kb0 = Kg + ((size_t)b * SS) * DD + h * HDIM;
    const float* Vb0 = Vg + ((size_t)b * SS) * DD + h * HDIM;
    const uint32_t* Mbase = mw + ((size_t)(bh * SS + q0)) * 32;

    #pragma unroll
    for (int i = 0; i < 8; i++) {
        int idx = tid + i * 256;
        int m = idx >> 4, c = (idx & 15) * 4;
        cp_async16(&Qs[m * LDQ + c], Qbase + (size_t)m * DD + c);
    }
    #pragma unroll
    for (int i = 0; i < 4; i++) {
        int idx = tid + i * 256;
        int m = idx >> 3, c = (idx & 7) * 4;
        cp_async16(&Mw[m * LDM + c], Mbase + (size_t)m * 32 + c);
    }
    #pragma unroll
    for (int i = 0; i < 2; i++) {
        int idx = tid + i * 256;
        int r = idx >> 4, c = (idx & 15) * 4;
        cp_async16(&Ks[r * LDQ + c], Kb0 + (size_t)r * DD + c);
        cp_async16(&Vs[r * LDV + c], Vb0 + (size_t)r * DD + c);
    }
    CP_COMMIT();

    float acc_o[4][2][4];
    #pragma unroll
    for (int mt = 0; mt < 4; mt++)
        #pragma unroll
        for (int nt = 0; nt < 2; nt++)
            #pragma unroll
            for (int i = 0; i < 4; i++) acc_o[mt][nt][i] = 0.f;
    float rs[8];
    #pragma unroll
    for (int i = 0; i < 8; i++) rs[i] = 0.f;

    const int nkt = SS / KTR;
    for (int kt = 0; kt < nkt; kt++) {
        const int buf = kt & 1;
        const float* Kb = Ks + buf * KS_T;
        const float* Vb = Vs + buf * VS_T;

        CP_WAIT0();
        __syncthreads();

        if (kt + 1 < nkt) {
            float* Kn = Ks + (buf ^ 1) * KS_T;
            float* Vn = Vs + (buf ^ 1) * VS_T;
            const float* Kt = Kb0 + (size_t)((kt + 1) * KTR) * DD;
            const float* Vt = Vb0 + (size_t)((kt + 1) * KTR) * DD;
            #pragma unroll
            for (int i = 0; i < 2; i++) {
                int idx = tid + i * 256;
                int r = idx >> 4, c = (idx & 15) * 4;
                cp_async16(&Kn[r * LDQ + c], Kt + (size_t)r * DD + c);
                cp_async16(&Vn[r * LDV + c], Vt + (size_t)r * DD + c);
            }
            CP_COMMIT();
        }

        /* S = Q(128x64) . K^T(32x64) -> 128x32; warp covers 64x8 */
        float acc_s[4][4];
        #pragma unroll
        for (int mt = 0; mt < 4; mt++)
            #pragma unroll
            for (int i = 0; i < 4; i++) acc_s[mt][i] = 0.f;

        #pragma unroll
        for (int kk = 0; kk < 64; kk += 8) {
            uint32_t af[4][4], bf[2];
            #pragma unroll
            for (int mt = 0; mt < 4; mt++) {
                int mb = wm * 64 + mt * 16 + g;
                float2 q0v = *(const float2*)&Qs[mb * LDQ + kk + 2 * t];
                float2 q1v = *(const float2*)&Qs[(mb + 8) * LDQ + kk + 2 * t];
                af[mt][0] = fu(q0v.x); af[mt][2] = fu(q0v.y);
                af[mt][1] = fu(q1v.x); af[mt][3] = fu(q1v.y);
            }
            {
                int nb = wn * 8 + g;
                float2 kv = *(const float2*)&Kb[nb * LDQ + kk + 2 * t];
                bf[0] = fu(kv.x); bf[1] = fu(kv.y);
            }
            #pragma unroll
            for (int mt = 0; mt < 4; mt++)
                mma_tf32(acc_s[mt], af[mt][0], af[mt][1], af[mt][2], af[mt][3],
                         bf[0], bf[1]);
        }

        /* mask(bits) + exp + store P + row-sum partials */
        const int col = wn * 8 + 2 * t;
        #pragma unroll
        for (int mt = 0; mt < 4; mt++) {
            #pragma unroll
            for (int half = 0; half < 2; half++) {
                const int row = wm * 64 + mt * 16 + g + half * 8;
                const uint32_t word = Mw[row * LDM + kt];
                float s0 = acc_s[mt][half * 2 + 0] * 0.125f;
                float s1 = acc_s[mt][half * 2 + 1] * 0.125f;
                float p0 = ((word >> col) & 1u) ? 0.f : __expf(s0);
                float p1 = ((word >> (col + 1)) & 1u) ? 0.f : __expf(s1);
                rs[mt * 2 + half] += p0 + p1;
                float2 pv; pv.x = to_tf32(p0); pv.y = to_tf32(p1);
                *(float2*)&Ps[row * LDP + col] = pv;
            }
        }
        __syncthreads();

        /* O += P(128x32) . V(32x64) */
        #pragma unroll
        for (int kk = 0; kk < 32; kk += 8) {
            uint32_t af[4][4], bf[2][2];
            #pragma unroll
            for (int mt = 0; mt < 4; mt++) {
                int mb = wm * 64 + mt * 16 + g;
                float2 p0v = *(const float2*)&Ps[mb * LDP + kk + 2 * t];
                float2 p1v = *(const float2*)&Ps[(mb + 8) * LDP + kk + 2 * t];
                af[mt][0] = fu(p0v.x); af[mt][2] = fu(p0v.y);
                af[mt][1] = fu(p1v.x); af[mt][3] = fu(p1v.y);
            }
            #pragma unroll
            for (int nt = 0; nt < 2; nt++) {
                int nb = wn * 16 + nt * 8 + g;
                bf[nt][0] = fu(Vb[(kk + 2 * t) * LDV + nb]);
                bf[nt][1] = fu(Vb[(kk + 2 * t + 1) * LDV + nb]);
            }
            #pragma unroll
            for (int mt = 0; mt < 4; mt++)
                #pragma unroll
                for (int nt = 0; nt < 2; nt++)
                    mma_tf32(acc_o[mt][nt], af[mt][0], af[mt][1], af[mt][2], af[mt][3],
                             bf[nt][0], bf[nt][1]);
        }
    }

    #pragma unroll
    for (int mt = 0; mt < 4; mt++)
        #pragma unroll
        for (int half = 0; half < 2; half++) {
            const int row = wm * 64 + mt * 16 + g + half * 8;
            atomicAdd(&rsum[row], rs[mt * 2 + half]);
        }
    __syncthreads();

    #pragma unroll
    for (int mt = 0; mt < 4; mt++) {
        #pragma unroll
        for (int half = 0; half < 2; half++) {
            const int row = wm * 64 + mt * 16 + g + half * 8;
            const float inv = 1.f / rsum[row];
            #pragma unroll
            for (int nt = 0; nt < 2; nt++) {
                const int c = wn * 16 + nt * 8 + 2 * t;
                float2 o;
                o.x = acc_o[mt][nt][half * 2 + 0] * inv;
                o.y = acc_o[mt][nt][half * 2 + 1] * inv;
                *(float2*)&ctx[((size_t)(b * SS + q0 + row)) * DD + h * HDIM + c] = o;
            }
        }
    }
}

/* ---------------- LayerNorm over D ---------------- */
__global__ void __launch_bounds__(256)
ln_kernel(const float* __restrict__ in, const float* __restrict__ g,
          const float* __restrict__ beta, float* __restrict__ out)
{
    __shared__ float red[8];
    const size_t base = (size_t)blockIdx.x * DD;
    const int tid = threadIdx.x;
    float v[4];
    #pragma unroll
    for (int i = 0; i < 4; i++) v[i] = in[base + tid + i * 256];

    float s = v[0] + v[1] + v[2] + v[3];
    const float mu = blockSum(s, red) * (1.f / DD);

    float sq = 0.f;
    #pragma unroll
    for (int i = 0; i < 4; i++) { v[i] -= mu; sq += v[i] * v[i]; }
    const float var = blockSum(sq, red) * (1.f / DD);
    const float r = rsqrtf(var + LN_EPS);

    #pragma unroll
    for (int i = 0; i < 4; i++) {
        int c = tid + i * 256;
        out[base + c] = v[i] * r * g[c] + beta[c];
    }
}

/* ---------------- launch ---------------- */
extern "C" void kernel_launch(void* const* d_in, const int* in_sizes, int n_in,
                              void* d_out, int out_size)
{
    const float* x    = (const float*)d_in[0];
    const float* y    = (const float*)d_in[1];
    const int* mask   = (const int*)d_in[2];
    const float* Wq = (const float*)d_in[3];
    const float* bq = (const float*)d_in[4];
    const float* Wk = (const float*)d_in[5];
    const float* bk = (const float*)d_in[6];
    const float* Wv = (const float*)d_in[7];
    const float* bv = (const float*)d_in[8];
    const float* Wo = (const float*)d_in[9];
    const float* bo = (const float*)d_in[10];
    const float* W1 = (const float*)d_in[11];
    const float* b1 = (const float*)d_in[12];
    const float* W2 = (const float*)d_in[13];
    const float* b2 = (const float*)d_in[14];
    const float* g1 = (const float*)d_in[15];
    const float* be1 = (const float*)d_in[16];
    const float* g2 = (const float*)d_in[17];
    const float* be2 = (const float*)d_in[18];
    float* out = (float*)d_out;

    cudaFuncSetAttribute(mma_gemm<0>, cudaFuncAttributeMaxDynamicSharedMemorySize, GEMM_SMEM);
    cudaFuncSetAttribute(mma_gemm<1>, cudaFuncAttributeMaxDynamicSharedMemorySize, GEMM_SMEM);
    cudaFuncSetAttribute(mma_gemm<2>, cudaFuncAttributeMaxDynamicSharedMemorySize, GEMM_SMEM);
    cudaFuncSetAttribute(mma_gemm_kv, cudaFuncAttributeMaxDynamicSharedMemorySize, GEMM_SMEM);
    cudaFuncSetAttribute(flash_attn, cudaFuncAttributeMaxDynamicSharedMemorySize, FL_SMEM);

    float* pool = nullptr;
    cudaGetSymbolAddress((void**)&pool, g_pool);
    float* q   = pool + OFF_Q;
    float* k   = pool + OFF_K;
    float* v   = pool + OFF_V;
    float* ctx = pool + OFF_CTX;
    float* x1  = pool + OFF_X1;
    float* tmp = pool + OFF_TMP;
    float* h   = pool + OFF_H;
    uint32_t* mw = (uint32_t*)(pool + OFF_MW);

    dim3 gProj(DD / 128, MROWS / 128);      /* 8 x 32 */
    dim3 gKV(DD / 128, MROWS / 128, 2);     /* 8 x 32 x 2 */
    dim3 gFF1(FFD / 128, MROWS / 128);      /* 32 x 32 */

    /* mask packing */
    mask_pack<<<32768, 256>>>(mask, mw);

    /* projections */
    mma_gemm<0><<<gProj, 256, GEMM_SMEM>>>(x, Wq, bq, nullptr, q, MROWS, DD, DD);
    mma_gemm_kv<<<gKV, 256, GEMM_SMEM>>>(y, Wk, bk, k, Wv, bv, v, MROWS, DD, DD);

    /* fused attention */
    flash_attn<<<dim3(SS / 128, BB * HH), 256, FL_SMEM>>>(q, k, v, mw, ctx);

    /* output proj + residual, LN1 */
    mma_gemm<2><<<gProj, 256, GEMM_SMEM>>>(ctx, Wo, bo, x, tmp, MROWS, DD, DD);
    ln_kernel<<<MROWS, 256>>>(tmp, g1, be1, x1);

    /* FFN */
    mma_gemm<1><<<gFF1, 256, GEMM_SMEM>>>(x1, W1, b1, nullptr, h, MROWS, FFD, DD);
    mma_gemm<2><<<gProj, 256, GEMM_SMEM>>>(h, W2, b2, x1, tmp, MROWS, DD, FFD);
    ln_kernel<<<MROWS, 256>>>(tmp, g2, be2, out);
}